// round 7
// baseline (speedup 1.0000x reference)
#include <cuda_runtime.h>
#include <math.h>

// Problem geometry (fixed by reference): T=1e6, D=82, 256 groups
#define D        82
#define NGROUP   256
#define NSTAT    6            // count, Sx, Sy, Sxx, Syy, Sxy
#define TPB      256          // 8 warps per block
#define WARPS_PER_BLOCK (TPB / 32)
#define BLOCKS_PER_SM 3
#define MAX_GRID   (148 * BLOCKS_PER_SM)   // 444

// Global scratch for group statistics: [NSTAT][NGROUP] doubles
__device__ double g_stats[NSTAT * NGROUP];

__global__ void zero_stats_kernel() {
    int i = blockIdx.x * blockDim.x + threadIdx.x;
    if (i < NSTAT * NGROUP) g_stats[i] = 0.0;
}

// Warp-per-row kernel: no shared staging, no per-tile barriers.
// Lanes read the row's float2s at consecutive addresses (fully coalesced),
// FMA against register-resident W, butterfly-reduce, lane 0 finishes
// (sqrt, pred store, 6 fp32 shared atomics). Per-block float partials are
// sums over ~2250/256 ~ 9 rows per group -> fp32 exact enough; promoted to
// double at the single per-block global flush.
__global__ __launch_bounds__(TPB, BLOCKS_PER_SM)
void pred_stats_kernel(const float* __restrict__ X1,
                       const float* __restrict__ X2,
                       const float* __restrict__ Y,
                       const float* __restrict__ W,
                       const int*   __restrict__ mask,
                       float* __restrict__ pred_out,   // may be null
                       int T, int totalWarps)
{
    __shared__ float sStat[NSTAT * NGROUP];   // 6 KB

    const int tid  = threadIdx.x;
    const int lane = tid & 31;
    const int gwarp = blockIdx.x * WARPS_PER_BLOCK + (tid >> 5);

    for (int i = tid; i < NSTAT * NGROUP; i += TPB) sStat[i] = 0.0f;
    __syncthreads();

    // Register-resident weights: lane l owns W[2l],W[2l+1] and (l<9) W[64+2l],W[65+2l]
    const float w0 = W[2 * lane];
    const float w1 = W[2 * lane + 1];
    float w2 = 0.0f, w3 = 0.0f;
    if (lane < (D - 64) / 2) {                // lanes 0..8
        w2 = W[64 + 2 * lane];
        w3 = W[65 + 2 * lane];
    }

    // Grid-stride over rows; adjacent warps own adjacent rows (line sharing in L1)
    for (int r = gwarp; r < T; r += totalWarps) {
        const float2* __restrict__ a = (const float2*)(X1 + (size_t)r * D);
        const float2* __restrict__ b = (const float2*)(X2 + (size_t)r * D);

        float2 ua = a[lane];
        float2 ub = b[lane];
        float d0 = ua.x - ub.x;
        float d1 = ua.y - ub.y;
        float s  = d0 * d0 * w0;
        s = fmaf(d1 * d1, w1, s);

        if (lane < (D - 64) / 2) {            // tail: elements 64..81
            float2 va = a[32 + lane];
            float2 vb = b[32 + lane];
            float e0 = va.x - vb.x;
            float e1 = va.y - vb.y;
            s = fmaf(e0 * e0, w2, s);
            s = fmaf(e1 * e1, w3, s);
        }

        // Butterfly reduction: all lanes end with the row sum
        #pragma unroll
        for (int ofs = 16; ofs > 0; ofs >>= 1)
            s += __shfl_xor_sync(0xFFFFFFFFu, s, ofs);

        if (lane == 0) {
            float x = sqrtf(s);
            if (pred_out) pred_out[r] = x;

            float y = Y[r];
            int   g = mask[r];
            atomicAdd(&sStat[0 * NGROUP + g], 1.0f);
            atomicAdd(&sStat[1 * NGROUP + g], x);
            atomicAdd(&sStat[2 * NGROUP + g], y);
            atomicAdd(&sStat[3 * NGROUP + g], x * x);
            atomicAdd(&sStat[4 * NGROUP + g], y * y);
            atomicAdd(&sStat[5 * NGROUP + g], x * y);
        }
    }

    __syncthreads();
    // One flush per block: promote float partials to global doubles
    for (int i = tid; i < NSTAT * NGROUP; i += TPB) {
        float v = sStat[i];
        if (v != 0.0f) atomicAdd(&g_stats[i], (double)v);
    }
}

// Per-group Pearson |r|, mean over groups -> coeff
__global__ __launch_bounds__(NGROUP)
void finalize_kernel(float* __restrict__ coeff_out)
{
    __shared__ double red[NGROUP];
    int g = threadIdx.x;

    double n   = g_stats[0 * NGROUP + g];
    double Sx  = g_stats[1 * NGROUP + g];
    double Sy  = g_stats[2 * NGROUP + g];
    double Sxx = g_stats[3 * NGROUP + g];
    double Syy = g_stats[4 * NGROUP + g];
    double Sxy = g_stats[5 * NGROUP + g];

    double nom = Sxy - Sx * Sy / n;
    double dx  = Sxx - Sx * Sx / n;
    double dy  = Syy - Sy * Sy / n;
    double r   = fabs(nom / sqrt(dx * dy));

    red[g] = r;
    __syncthreads();
    #pragma unroll
    for (int ofs = NGROUP / 2; ofs > 0; ofs >>= 1) {
        if (g < ofs) red[g] += red[g + ofs];
        __syncthreads();
    }
    if (g == 0 && coeff_out) coeff_out[0] = (float)(red[0] / (double)NGROUP);
}

extern "C" void kernel_launch(void* const* d_in, const int* in_sizes, int n_in,
                              void* d_out, int out_size)
{
    const float* X1   = (const float*)d_in[0];
    const float* X2   = (const float*)d_in[1];
    const float* Y    = (const float*)d_in[2];
    const float* W    = (const float*)d_in[3];
    const int*   mask = (const int*)  d_in[4];

    int T = in_sizes[0] / D;

    float* out = (float*)d_out;
    float* coeff_out = nullptr;
    float* pred_out  = nullptr;
    if (out_size == T + 1) {            // (coeff, pred) flattened in return order
        coeff_out = out;
        pred_out  = out + 1;
    } else if (out_size == T) {         // pred only
        pred_out  = out;
    } else {                            // coeff only
        coeff_out = out;
    }

    zero_stats_kernel<<<(NSTAT * NGROUP + 255) / 256, 256>>>();

    int totalWarps = MAX_GRID * WARPS_PER_BLOCK;
    pred_stats_kernel<<<MAX_GRID, TPB>>>(X1, X2, Y, W, mask, pred_out,
                                         T, totalWarps);

    finalize_kernel<<<1, NGROUP>>>(coeff_out);
}

// round 8
// speedup vs baseline: 2.3218x; 2.3218x over previous
#include <cuda_runtime.h>
#include <math.h>

// Problem geometry (fixed by reference): T=1e6, D=82, 256 groups
#define D        82
#define NGROUP   256
#define NSTAT    6            // count, Sx, Sy, Sxx, Syy, Sxy
#define TPB      96           // threads per block == rows per tile
#define ROWS     96
#define TILE_ELEMS (ROWS * D)        // 7872 floats = 31.5 KB
#define BLOCKS_PER_SM 3
#define MAX_GRID   (148 * BLOCKS_PER_SM)   // 444

// Global scratch for group statistics: [NSTAT][NGROUP] doubles
__device__ double g_stats[NSTAT * NGROUP];

__global__ void zero_stats_kernel() {
    int i = blockIdx.x * blockDim.x + threadIdx.x;
    if (i < NSTAT * NGROUP) g_stats[i] = 0.0;
}

// Double-buffered persistent kernel: while tile k is computed out of one
// shared buffer, tile k+1 is streamed (coalesced float4 LDGs) into the other.
// One barrier per tile -> each block keeps DRAM requests in flight
// continuously instead of alternating stream/compute phases.
// Stats accumulate in float shared atomics (per-block partials, fp32 exact
// enough), promoted to double at the single per-block global flush.
__global__ __launch_bounds__(TPB, BLOCKS_PER_SM)
void pred_stats_kernel(const float4* __restrict__ X1,
                       const float4* __restrict__ X2,
                       const float*  __restrict__ Y,
                       const float*  __restrict__ W,
                       const int*    __restrict__ mask,
                       float* __restrict__ pred_out,   // may be null
                       int T, int numTiles)
{
    __shared__ __align__(16) float sDiff[2][TILE_ELEMS];  // 63 KB
    __shared__ float sStat[NSTAT * NGROUP];               // 6 KB
    __shared__ float sW[D];

    const int tid = threadIdx.x;

    for (int i = tid; i < NSTAT * NGROUP; i += TPB) sStat[i] = 0.0f;
    if (tid < D) sW[tid] = W[tid];

    // Tiles owned by this block: tile_j = blockIdx.x + j*gridDim.x
    const int firstTile = blockIdx.x;
    if (firstTile >= numTiles) {          // (never happens at this size)
        __syncthreads();
        return;
    }

    // ---- stage helper (expanded inline twice below) ----
#define STAGE(tileIdx, buf)                                                  \
    do {                                                                     \
        const int _row0 = (tileIdx) * ROWS;                                  \
        const int _rows = min(ROWS, T - _row0);                              \
        const int _n4   = (_rows * D) / 4;                                   \
        const size_t _b4 = (size_t)_row0 * D / 4;                            \
        const float4* __restrict__ _A = X1 + _b4;                            \
        const float4* __restrict__ _B = X2 + _b4;                            \
        float4* __restrict__ _S = reinterpret_cast<float4*>(sDiff[buf]);     \
        _Pragma("unroll 4")                                                  \
        for (int _i = tid; _i < _n4; _i += TPB) {                            \
            float4 _a = _A[_i];                                              \
            float4 _b = _B[_i];                                              \
            float4 _d;                                                       \
            _d.x = _a.x - _b.x; _d.x *= _d.x;                                \
            _d.y = _a.y - _b.y; _d.y *= _d.y;                                \
            _d.z = _a.z - _b.z; _d.z *= _d.z;                                \
            _d.w = _a.w - _b.w; _d.w *= _d.w;                                \
            _S[_i] = _d;                                                     \
        }                                                                    \
    } while (0)

    __syncthreads();                 // sStat/sW init visible
    STAGE(firstTile, 0);             // prologue: stage first tile into buf 0

    int k = 0;
    for (int tile = firstTile; tile < numTiles; tile += gridDim.x, k++) {
        const int cur = k & 1;
        const int row0 = tile * ROWS;
        const int rows = min(ROWS, T - row0);
        const int t    = row0 + tid;

        __syncthreads();   // buf[cur] staged; buf[cur^1]'s previous compute done

        // Issue this tile's Y/mask loads early (overlap with next-tile staging)
        float yReg = 0.0f; int gReg = 0;
        if (tid < rows) { yReg = Y[t]; gReg = mask[t]; }

        // Stage NEXT tile into the other buffer (LDGs go out first)
        const int nextTile = tile + gridDim.x;
        if (nextTile < numTiles) STAGE(nextTile, cur ^ 1);

        // Compute current tile: one row per thread (2-way bank conflict max)
        if (tid < rows) {
            const float2* __restrict__ dd =
                reinterpret_cast<const float2*>(sDiff[cur] + tid * D);
            float s = 0.0f;
            #pragma unroll
            for (int i = 0; i < D / 2; i++) {
                float2 v = dd[i];
                s = fmaf(v.x, sW[2 * i],     s);
                s = fmaf(v.y, sW[2 * i + 1], s);
            }
            float x = sqrtf(s);
            if (pred_out) pred_out[t] = x;

            const int g = gReg;
            const float y = yReg;
            atomicAdd(&sStat[0 * NGROUP + g], 1.0f);
            atomicAdd(&sStat[1 * NGROUP + g], x);
            atomicAdd(&sStat[2 * NGROUP + g], y);
            atomicAdd(&sStat[3 * NGROUP + g], s);       // x*x == s (to rounding)
            atomicAdd(&sStat[4 * NGROUP + g], y * y);
            atomicAdd(&sStat[5 * NGROUP + g], x * y);
        }
    }
#undef STAGE

    __syncthreads();
    // One flush per persistent block: promote float partials to global doubles
    for (int i = tid; i < NSTAT * NGROUP; i += TPB) {
        float v = sStat[i];
        if (v != 0.0f) atomicAdd(&g_stats[i], (double)v);
    }
}

// Per-group Pearson |r|, mean over groups -> coeff
__global__ __launch_bounds__(NGROUP)
void finalize_kernel(float* __restrict__ coeff_out)
{
    __shared__ double red[NGROUP];
    int g = threadIdx.x;

    double n   = g_stats[0 * NGROUP + g];
    double Sx  = g_stats[1 * NGROUP + g];
    double Sy  = g_stats[2 * NGROUP + g];
    double Sxx = g_stats[3 * NGROUP + g];
    double Syy = g_stats[4 * NGROUP + g];
    double Sxy = g_stats[5 * NGROUP + g];

    double nom = Sxy - Sx * Sy / n;
    double dx  = Sxx - Sx * Sx / n;
    double dy  = Syy - Sy * Sy / n;
    double r   = fabs(nom / sqrt(dx * dy));

    red[g] = r;
    __syncthreads();
    #pragma unroll
    for (int ofs = NGROUP / 2; ofs > 0; ofs >>= 1) {
        if (g < ofs) red[g] += red[g + ofs];
        __syncthreads();
    }
    if (g == 0 && coeff_out) coeff_out[0] = (float)(red[0] / (double)NGROUP);
}

extern "C" void kernel_launch(void* const* d_in, const int* in_sizes, int n_in,
                              void* d_out, int out_size)
{
    const float* X1   = (const float*)d_in[0];
    const float* X2   = (const float*)d_in[1];
    const float* Y    = (const float*)d_in[2];
    const float* W    = (const float*)d_in[3];
    const int*   mask = (const int*)  d_in[4];

    int T = in_sizes[0] / D;

    float* out = (float*)d_out;
    float* coeff_out = nullptr;
    float* pred_out  = nullptr;
    if (out_size == T + 1) {            // (coeff, pred) flattened in return order
        coeff_out = out;
        pred_out  = out + 1;
    } else if (out_size == T) {         // pred only
        pred_out  = out;
    } else {                            // coeff only
        coeff_out = out;
    }

    zero_stats_kernel<<<(NSTAT * NGROUP + 255) / 256, 256>>>();

    int numTiles = (T + ROWS - 1) / ROWS;
    int grid = numTiles < MAX_GRID ? numTiles : MAX_GRID;
    pred_stats_kernel<<<grid, TPB>>>((const float4*)X1, (const float4*)X2,
                                     Y, W, mask, pred_out, T, numTiles);

    finalize_kernel<<<1, NGROUP>>>(coeff_out);
}